// round 3
// baseline (speedup 1.0000x reference)
#include <cuda_runtime.h>
#include <cuda_bf16.h>
#include <cstdint>

// ============================================================================
// Problem: x(8,4096,768) fp32 -> quantize int8 -> GEMM vs weight_t(768,768) int8
//          -> int32 acc * 2e-4 + bias -> fp32 out (32768, 768)
// Baseline-PTX only (harness compiles at compute_103: no tcgen05/'a' features).
// Ampere-style mma.sync int8 GEMM with cp.async pipeline.
// The harness may promote the int8 weight tensor to int32/float32 — detect.
// ============================================================================
static constexpr int N_TOK = 32768;
static constexpr int KDIM  = 768;
static constexpr int MDIM  = 768;

static constexpr int TM = 128;      // token tile
static constexpr int TN = 128;      // out-col tile
static constexpr int TK = 64;       // K bytes per stage
static constexpr int STAGES = 3;
static constexpr int NSTAGE_ITERS = KDIM / TK;   // 12
static constexpr int ROWPAD = 80;   // 64B data padded to 80B: conflict-free ldmatrix
static constexpr int TILE_BYTES = TM * ROWPAD;          // 10240
static constexpr int STAGE_BYTES = 2 * TILE_BYTES;      // 20480 (A + B)
static constexpr int SMEM_TOTAL = STAGES * STAGE_BYTES; // 61440

// Scratch (__device__ globals: the allowed allocation-free path)
__device__ int8_t g_xq[(size_t)N_TOK * KDIM];   // quantized activations [N,K]
__device__ int8_t g_wb[(size_t)MDIM * KDIM];    // weight transposed to [M,K]
__device__ int    g_wmode;                       // 0=int8, 1=int32, 2=float32

// ============================================================================
// PTX helpers (all baseline: sm_75/sm_80 era, safe at compute_103)
// ============================================================================
__device__ __forceinline__ uint32_t smem_to_u32(const void* p) {
    uint32_t a;
    asm("{ .reg .u64 t; cvta.to.shared.u64 t, %1; cvt.u32.u64 %0, t; }" : "=r"(a) : "l"(p));
    return a;
}

__device__ __forceinline__ void cp_async16(uint32_t dst, const void* src) {
    asm volatile("cp.async.cg.shared.global [%0], [%1], 16;" :: "r"(dst), "l"(src));
}
#define CP_COMMIT() asm volatile("cp.async.commit_group;" ::: "memory")
#define CP_WAIT1()  asm volatile("cp.async.wait_group 1;" ::: "memory")

__device__ __forceinline__ void ldmatrix_x4(uint32_t* r, uint32_t addr) {
    asm volatile("ldmatrix.sync.aligned.m8n8.x4.shared.b16 {%0,%1,%2,%3}, [%4];"
                 : "=r"(r[0]), "=r"(r[1]), "=r"(r[2]), "=r"(r[3]) : "r"(addr));
}
__device__ __forceinline__ void ldmatrix_x2(uint32_t* r, uint32_t addr) {
    asm volatile("ldmatrix.sync.aligned.m8n8.x2.shared.b16 {%0,%1}, [%2];"
                 : "=r"(r[0]), "=r"(r[1]) : "r"(addr));
}

__device__ __forceinline__ void mma_s8(int* c, const uint32_t* a, const uint32_t* b) {
    asm volatile(
        "mma.sync.aligned.m16n8k32.row.col.s32.s8.s8.s32 "
        "{%0,%1,%2,%3}, {%4,%5,%6,%7}, {%8,%9}, {%0,%1,%2,%3};"
        : "+r"(c[0]), "+r"(c[1]), "+r"(c[2]), "+r"(c[3])
        : "r"(a[0]), "r"(a[1]), "r"(a[2]), "r"(a[3]), "r"(b[0]), "r"(b[1]));
}

// ============================================================================
// Kernel 0: detect the on-device dtype of the "int8" weight tensor.
// The harness supports float32/int32/bfloat16 — int8 is likely promoted.
//  - int32-promoted: every 4-byte word, as int32, lies in [-128, 127]
//  - float32-promoted: every word, as float, is integral in [-128, 127]
//  - otherwise: genuine int8 bytes
// Sampling 4096 words: false positive prob for random int8 bytes ~ (2^-24)^4096.
// ============================================================================
__global__ __launch_bounds__(256) void detect_kernel(const void* __restrict__ w) {
    __shared__ int v32, vf32;
    if (threadIdx.x == 0) { v32 = 0; vf32 = 0; }
    __syncthreads();
    const int32_t* wi = (const int32_t*)w;
    const float*   wf = (const float*)w;
    int c32 = 0, cf32 = 0;
    for (int i = threadIdx.x; i < 4096; i += 256) {
        int32_t a = wi[i];
        if (a >= -128 && a <= 127) c32++;
        float f = wf[i];
        if (f == rintf(f) && f >= -128.f && f <= 127.f) cf32++;
    }
    atomicAdd(&v32, c32);
    atomicAdd(&vf32, cf32);
    __syncthreads();
    if (threadIdx.x == 0) {
        g_wmode = (v32 == 4096) ? 1 : ((vf32 == 4096) ? 2 : 0);
    }
}

// ============================================================================
// Kernel 1: quantize x -> int8. Exactly mirrors reference:
// q = clamp(round(x / 0.02f), -128, 127) with IEEE fp32 division.
// ============================================================================
__global__ __launch_bounds__(256) void quant_kernel(const float* __restrict__ x) {
    const int n4 = (N_TOK * KDIM) / 4;
    int i = blockIdx.x * blockDim.x + threadIdx.x;
    if (i >= n4) return;
    float4 v = reinterpret_cast<const float4*>(x)[i];
    float r0 = fminf(fmaxf(rintf(__fdiv_rn(v.x, 0.02f)), -128.f), 127.f);
    float r1 = fminf(fmaxf(rintf(__fdiv_rn(v.y, 0.02f)), -128.f), 127.f);
    float r2 = fminf(fmaxf(rintf(__fdiv_rn(v.z, 0.02f)), -128.f), 127.f);
    float r3 = fminf(fmaxf(rintf(__fdiv_rn(v.w, 0.02f)), -128.f), 127.f);
    int q0 = (int)r0, q1 = (int)r1, q2 = (int)r2, q3 = (int)r3;
    uint32_t packed = (uint32_t)(q0 & 0xFF) | ((uint32_t)(q1 & 0xFF) << 8) |
                      ((uint32_t)(q2 & 0xFF) << 16) | ((uint32_t)(q3 & 0xFF) << 24);
    reinterpret_cast<uint32_t*>(g_xq)[i] = packed;
}

// ============================================================================
// Kernel 2: transpose weight [K,M] -> [M,K] int8 (smem-tiled, 32x32),
// reading the source per detected dtype.
// ============================================================================
__global__ __launch_bounds__(256) void wtrans_kernel(const void* __restrict__ wsrc) {
    __shared__ int8_t t[32][33];
    const int kb = blockIdx.x * 32, mb = blockIdx.y * 32;
    const int tx = threadIdx.x & 31, ty = threadIdx.x >> 5;   // ty in 0..7
    const int mode = g_wmode;
    const int8_t*  w8 = (const int8_t*)wsrc;
    const int32_t* wi = (const int32_t*)wsrc;
    const float*   wf = (const float*)wsrc;
#pragma unroll
    for (int i = 0; i < 4; ++i) {
        int r = ty + i * 8;                     // K offset within tile
        size_t idx = (size_t)(kb + r) * MDIM + mb + tx;
        int8_t v;
        if (mode == 1)      v = (int8_t)wi[idx];
        else if (mode == 2) v = (int8_t)(int)wf[idx];
        else                v = w8[idx];
        t[r][tx] = v;
    }
    __syncthreads();
#pragma unroll
    for (int i = 0; i < 4; ++i) {
        int r = ty + i * 8;                     // M offset within tile
        g_wb[(size_t)(mb + r) * KDIM + kb + tx] = t[tx][r];
    }
}

// ============================================================================
// Kernel 3: int8 GEMM. CTA: 128 tokens x 128 cols, 256 threads (8 warps, 2x4),
// warp tile 64x32 = 4x4 mma(16x8) frags. 3-stage cp.async pipeline over K.
// ============================================================================
__global__ __launch_bounds__(256, 2)
void gemm_kernel(const float* __restrict__ bias, float* __restrict__ out) {
    extern __shared__ char smem[];
    const uint32_t sbase = smem_to_u32(smem);
    const int tid  = threadIdx.x;
    const int lane = tid & 31;
    const int warp = tid >> 5;
    const int wm = warp >> 2;          // 0..1 : token (M of mma) quadrant
    const int wn = warp & 3;           // 0..3 : out-col (N of mma) quadrant
    const int m0 = blockIdx.x * TN;    // output column tile
    const int n0 = blockIdx.y * TM;    // token tile

    auto load_stage = [&](int s) {
        const int buf = s % STAGES;
        const uint32_t sa = sbase + buf * STAGE_BYTES;
        const uint32_t sb = sa + TILE_BYTES;
        const int k0 = s * TK;
#pragma unroll
        for (int it = 0; it < 2; ++it) {
            int g   = tid + it * 256;       // 0..511
            int row = g >> 2;
            int c   = g & 3;
            cp_async16(sa + row * ROWPAD + c * 16,
                       g_xq + (size_t)(n0 + row) * KDIM + k0 + c * 16);
            cp_async16(sb + row * ROWPAD + c * 16,
                       g_wb + (size_t)(m0 + row) * KDIM + k0 + c * 16);
        }
    };

    int acc[4][4][4];
#pragma unroll
    for (int i = 0; i < 4; ++i)
#pragma unroll
        for (int j = 0; j < 4; ++j)
#pragma unroll
            for (int k = 0; k < 4; ++k) acc[i][j][k] = 0;

    load_stage(0); CP_COMMIT();
    load_stage(1); CP_COMMIT();

    const int a_row = (lane & 7) + ((lane >> 3) & 1) * 8;   // 0..15
    const int a_kb  = (lane >> 4) * 16;                     // 0 or 16
    const int b_row = lane & 7;
    const int b_kb  = ((lane >> 3) & 1) * 16;

    for (int s = 0; s < NSTAGE_ITERS; ++s) {
        CP_WAIT1();
        __syncthreads();
        if (s + 2 < NSTAGE_ITERS) load_stage(s + 2);
        CP_COMMIT();

        const int buf = s % STAGES;
        const uint32_t sa = sbase + buf * STAGE_BYTES;
        const uint32_t sb = sa + TILE_BYTES;
#pragma unroll
        for (int kk = 0; kk < 2; ++kk) {   // two k32 steps per 64B stage
            uint32_t afrag[4][4], bfrag[4][2];
            const uint32_t abase =
                sa + (uint32_t)(wm * 64 + a_row) * ROWPAD + kk * 32 + a_kb;
#pragma unroll
            for (int mf = 0; mf < 4; ++mf)
                ldmatrix_x4(afrag[mf], abase + (uint32_t)mf * 16 * ROWPAD);
            const uint32_t bbase =
                sb + (uint32_t)(wn * 32 + b_row) * ROWPAD + kk * 32 + b_kb;
#pragma unroll
            for (int nf = 0; nf < 4; ++nf)
                ldmatrix_x2(bfrag[nf], bbase + (uint32_t)nf * 8 * ROWPAD);
#pragma unroll
            for (int mf = 0; mf < 4; ++mf)
#pragma unroll
                for (int nf = 0; nf < 4; ++nf)
                    mma_s8(acc[mf][nf], afrag[mf], bfrag[nf]);
        }
        __syncthreads();
    }

    // ---- epilogue: dequant + bias, float2 stores
    const float eff = (float)(0.02 * 0.01);
    float2 bv[4];
#pragma unroll
    for (int nf = 0; nf < 4; ++nf) {
        const int col = m0 + wn * 32 + nf * 8 + 2 * (lane & 3);
        bv[nf].x = __ldg(bias + col);
        bv[nf].y = __ldg(bias + col + 1);
    }
#pragma unroll
    for (int mf = 0; mf < 4; ++mf) {
        const int row_lo = n0 + wm * 64 + mf * 16 + (lane >> 2);
        float* p_lo = out + (size_t)row_lo * MDIM;
        float* p_hi = p_lo + 8 * MDIM;
#pragma unroll
        for (int nf = 0; nf < 4; ++nf) {
            const int col = m0 + wn * 32 + nf * 8 + 2 * (lane & 3);
            float2 lo, hi;
            lo.x = (float)acc[mf][nf][0] * eff + bv[nf].x;
            lo.y = (float)acc[mf][nf][1] * eff + bv[nf].y;
            hi.x = (float)acc[mf][nf][2] * eff + bv[nf].x;
            hi.y = (float)acc[mf][nf][3] * eff + bv[nf].y;
            *reinterpret_cast<float2*>(p_lo + col) = lo;
            *reinterpret_cast<float2*>(p_hi + col) = hi;
        }
    }
}

// ============================================================================
// Launch
// ============================================================================
extern "C" void kernel_launch(void* const* d_in, const int* in_sizes, int n_in,
                              void* d_out, int out_size) {
    const float* x    = (const float*)d_in[0];
    const void*  wt   = d_in[1];
    const float* bias = (const float*)d_in[2];
    float*       out  = (float*)d_out;

    cudaFuncSetAttribute(gemm_kernel, cudaFuncAttributeMaxDynamicSharedMemorySize,
                         SMEM_TOTAL);

    detect_kernel<<<1, 256>>>(wt);
    {
        int n4 = (N_TOK * KDIM) / 4;
        quant_kernel<<<(n4 + 255) / 256, 256>>>(x);
    }
    {
        dim3 grid(KDIM / 32, MDIM / 32);
        wtrans_kernel<<<grid, 256>>>(wt);
    }
    {
        dim3 grid(MDIM / TN, N_TOK / TM);   // (6, 256)
        gemm_kernel<<<grid, 256, SMEM_TOTAL>>>(bias, out);
    }
    (void)in_sizes; (void)n_in; (void)out_size;
}

// round 4
// speedup vs baseline: 1.0571x; 1.0571x over previous
#include <cuda_runtime.h>
#include <cuda_bf16.h>
#include <cstdint>

// ============================================================================
// x(8,4096,768) fp32 -> int8 quant -> GEMM vs weight_t(768,768) int8 (promoted
// to int32/fp32 by harness; detected) -> int32 acc * 2e-4 + bias -> fp32 out.
// Legacy mma.sync int8 path (compute_103 baseline PTX; tcgen05 unavailable).
// R4: wave-quantization fix. 3072 tiles of 128tok x 64col, 128-thread CTAs,
// resident capped at 2 CTAs/SM via 76.8KB smem (5-stage cp.async pipeline).
// 3072/296 = 10.38 waves -> 94.3% wave efficiency (was 5.19/6 = 86.5%).
// ============================================================================
static constexpr int N_TOK = 32768;
static constexpr int KDIM  = 768;
static constexpr int MDIM  = 768;

static constexpr int TM = 128;      // token tile
static constexpr int TN = 64;       // out-col tile
static constexpr int TK = 64;       // K bytes per stage
static constexpr int STAGES = 5;
static constexpr int NSTAGE_ITERS = KDIM / TK;   // 12
static constexpr int ROWPAD = 80;   // 64B data padded to 80B: conflict-free ldmatrix
static constexpr int A_TILE_BYTES = TM * ROWPAD;        // 10240
static constexpr int B_TILE_BYTES = TN * ROWPAD;        // 5120
static constexpr int STAGE_BYTES  = A_TILE_BYTES + B_TILE_BYTES;  // 15360
static constexpr int SMEM_TOTAL   = STAGES * STAGE_BYTES;         // 76800 -> 2 CTA/SM

// Scratch (__device__ globals: the allowed allocation-free path)
__device__ int8_t g_xq[(size_t)N_TOK * KDIM];   // quantized activations [N,K]
__device__ int8_t g_wb[(size_t)MDIM * KDIM];    // weight transposed to [M,K]

// ============================================================================
// PTX helpers (baseline sm_75/sm_80 era, safe at compute_103)
// ============================================================================
__device__ __forceinline__ uint32_t smem_to_u32(const void* p) {
    uint32_t a;
    asm("{ .reg .u64 t; cvta.to.shared.u64 t, %1; cvt.u32.u64 %0, t; }" : "=r"(a) : "l"(p));
    return a;
}

__device__ __forceinline__ void cp_async16(uint32_t dst, const void* src) {
    asm volatile("cp.async.cg.shared.global [%0], [%1], 16;" :: "r"(dst), "l"(src));
}
#define CP_COMMIT() asm volatile("cp.async.commit_group;" ::: "memory")
#define CP_WAIT3()  asm volatile("cp.async.wait_group 3;" ::: "memory")

__device__ __forceinline__ void ldmatrix_x4(uint32_t* r, uint32_t addr) {
    asm volatile("ldmatrix.sync.aligned.m8n8.x4.shared.b16 {%0,%1,%2,%3}, [%4];"
                 : "=r"(r[0]), "=r"(r[1]), "=r"(r[2]), "=r"(r[3]) : "r"(addr));
}
__device__ __forceinline__ void ldmatrix_x2(uint32_t* r, uint32_t addr) {
    asm volatile("ldmatrix.sync.aligned.m8n8.x2.shared.b16 {%0,%1}, [%2];"
                 : "=r"(r[0]), "=r"(r[1]) : "r"(addr));
}

__device__ __forceinline__ void mma_s8(int* c, const uint32_t* a, const uint32_t* b) {
    asm volatile(
        "mma.sync.aligned.m16n8k32.row.col.s32.s8.s8.s32 "
        "{%0,%1,%2,%3}, {%4,%5,%6,%7}, {%8,%9}, {%0,%1,%2,%3};"
        : "+r"(c[0]), "+r"(c[1]), "+r"(c[2]), "+r"(c[3])
        : "r"(a[0]), "r"(a[1]), "r"(a[2]), "r"(a[3]), "r"(b[0]), "r"(b[1]));
}

// ============================================================================
// Kernel 1: quantize x -> int8. q = clamp(round(x / 0.02f), -128, 127),
// IEEE fp32 division to mirror the reference bit-for-bit.
// ============================================================================
__global__ __launch_bounds__(256) void quant_kernel(const float* __restrict__ x) {
    const int n4 = (N_TOK * KDIM) / 4;
    int i = blockIdx.x * blockDim.x + threadIdx.x;
    if (i >= n4) return;
    float4 v = reinterpret_cast<const float4*>(x)[i];
    float r0 = fminf(fmaxf(rintf(__fdiv_rn(v.x, 0.02f)), -128.f), 127.f);
    float r1 = fminf(fmaxf(rintf(__fdiv_rn(v.y, 0.02f)), -128.f), 127.f);
    float r2 = fminf(fmaxf(rintf(__fdiv_rn(v.z, 0.02f)), -128.f), 127.f);
    float r3 = fminf(fmaxf(rintf(__fdiv_rn(v.w, 0.02f)), -128.f), 127.f);
    int q0 = (int)r0, q1 = (int)r1, q2 = (int)r2, q3 = (int)r3;
    uint32_t packed = (uint32_t)(q0 & 0xFF) | ((uint32_t)(q1 & 0xFF) << 8) |
                      ((uint32_t)(q2 & 0xFF) << 16) | ((uint32_t)(q3 & 0xFF) << 24);
    reinterpret_cast<uint32_t*>(g_xq)[i] = packed;
}

// ============================================================================
// Kernel 2: transpose weight [K,M] -> [M,K] int8, with inline dtype detection
// (the harness promotes int8 tensors; each block samples 1024 words — L2-hot).
// ============================================================================
__global__ __launch_bounds__(256) void wtrans_kernel(const void* __restrict__ wsrc) {
    __shared__ int8_t t[32][33];
    __shared__ int s_mode;
    // detection: int32-promoted iff every sampled word in [-128,127];
    // fp32-promoted iff every sampled word is an integral float in range.
    {
        const int32_t* wi = (const int32_t*)wsrc;
        const float*   wf = (const float*)wsrc;
        bool ok32 = true, okf = true;
        for (int i = threadIdx.x; i < 1024; i += 256) {
            int32_t a = wi[i];
            ok32 &= (a >= -128 && a <= 127);
            float f = wf[i];
            okf  &= (f == rintf(f) && f >= -128.f && f <= 127.f);
        }
        ok32 = __syncthreads_and(ok32);
        okf  = __syncthreads_and(okf);
        if (threadIdx.x == 0) s_mode = ok32 ? 1 : (okf ? 2 : 0);
        __syncthreads();
    }
    const int mode = s_mode;
    const int kb = blockIdx.x * 32, mb = blockIdx.y * 32;
    const int tx = threadIdx.x & 31, ty = threadIdx.x >> 5;   // ty in 0..7
    const int8_t*  w8 = (const int8_t*)wsrc;
    const int32_t* wi = (const int32_t*)wsrc;
    const float*   wf = (const float*)wsrc;
#pragma unroll
    for (int i = 0; i < 4; ++i) {
        int r = ty + i * 8;
        size_t idx = (size_t)(kb + r) * MDIM + mb + tx;
        int8_t v;
        if (mode == 1)      v = (int8_t)wi[idx];
        else if (mode == 2) v = (int8_t)(int)wf[idx];
        else                v = w8[idx];
        t[r][tx] = v;
    }
    __syncthreads();
#pragma unroll
    for (int i = 0; i < 4; ++i) {
        int r = ty + i * 8;
        g_wb[(size_t)(mb + r) * KDIM + kb + tx] = t[tx][r];
    }
}

// ============================================================================
// Kernel 3: int8 GEMM. CTA: 128 tokens x 64 cols, 128 threads (4 warps, 2x2),
// warp tile 64x32 = 4x4 mma(16x8x32) frags. 5-stage cp.async, 1 sync/stage.
// ============================================================================
__global__ __launch_bounds__(128, 2)
void gemm_kernel(const float* __restrict__ bias, float* __restrict__ out) {
    extern __shared__ char smem[];
    const uint32_t sbase = smem_to_u32(smem);
    const int tid  = threadIdx.x;
    const int lane = tid & 31;
    const int warp = tid >> 5;
    const int wm = warp >> 1;          // 0..1 : token half (64 rows)
    const int wn = warp & 1;           // 0..1 : col half (32 cols)
    const int m0 = blockIdx.x * TN;    // output column tile (12)
    const int n0 = blockIdx.y * TM;    // token tile (256)

    // stage loader: A 512 chunks + B 256 chunks of 16B = 768 / 128 thr = 6 each
    auto load_stage = [&](int s) {
        const int buf = s % STAGES;
        const uint32_t sa = sbase + buf * STAGE_BYTES;
        const uint32_t sb = sa + A_TILE_BYTES;
        const int k0 = s * TK;
#pragma unroll
        for (int it = 0; it < 6; ++it) {
            int g = tid + it * 128;          // 0..767
            if (g < 512) {
                int row = g >> 2, c = g & 3;
                cp_async16(sa + row * ROWPAD + c * 16,
                           g_xq + (size_t)(n0 + row) * KDIM + k0 + c * 16);
            } else {
                int h = g - 512;
                int row = h >> 2, c = h & 3;
                cp_async16(sb + row * ROWPAD + c * 16,
                           g_wb + (size_t)(m0 + row) * KDIM + k0 + c * 16);
            }
        }
    };

    int acc[4][4][4];
#pragma unroll
    for (int i = 0; i < 4; ++i)
#pragma unroll
        for (int j = 0; j < 4; ++j)
#pragma unroll
            for (int k = 0; k < 4; ++k) acc[i][j][k] = 0;

    load_stage(0); CP_COMMIT();
    load_stage(1); CP_COMMIT();
    load_stage(2); CP_COMMIT();
    load_stage(3); CP_COMMIT();

    const int a_row = (lane & 7) + ((lane >> 3) & 1) * 8;   // 0..15
    const int a_kb  = (lane >> 4) * 16;                     // 0 or 16
    const int b_row = lane & 7;
    const int b_kb  = ((lane >> 3) & 1) * 16;

    for (int s = 0; s < NSTAGE_ITERS; ++s) {
        CP_WAIT3();                 // stage s complete (<=3 groups pending)
        __syncthreads();            // also guards buffer (s-1)%5 fully consumed
        if (s + 4 < NSTAGE_ITERS) load_stage(s + 4);
        CP_COMMIT();                // unconditional: keeps group accounting fixed

        const int buf = s % STAGES;
        const uint32_t sa = sbase + buf * STAGE_BYTES;
        const uint32_t sb = sa + A_TILE_BYTES;
#pragma unroll
        for (int kk = 0; kk < 2; ++kk) {   // two k32 steps per 64B stage
            uint32_t afrag[4][4], bfrag[4][2];
            const uint32_t abase =
                sa + (uint32_t)(wm * 64 + a_row) * ROWPAD + kk * 32 + a_kb;
#pragma unroll
            for (int mf = 0; mf < 4; ++mf)
                ldmatrix_x4(afrag[mf], abase + (uint32_t)mf * 16 * ROWPAD);
            const uint32_t bbase =
                sb + (uint32_t)(wn * 32 + b_row) * ROWPAD + kk * 32 + b_kb;
#pragma unroll
            for (int nf = 0; nf < 4; ++nf)
                ldmatrix_x2(bfrag[nf], bbase + (uint32_t)nf * 8 * ROWPAD);
#pragma unroll
            for (int mf = 0; mf < 4; ++mf)
#pragma unroll
                for (int nf = 0; nf < 4; ++nf)
                    mma_s8(acc[mf][nf], afrag[mf], bfrag[nf]);
        }
    }

    // ---- epilogue: dequant + bias, float2 stores
    const float eff = (float)(0.02 * 0.01);
    float2 bv[4];
#pragma unroll
    for (int nf = 0; nf < 4; ++nf) {
        const int col = m0 + wn * 32 + nf * 8 + 2 * (lane & 3);
        bv[nf].x = __ldg(bias + col);
        bv[nf].y = __ldg(bias + col + 1);
    }
#pragma unroll
    for (int mf = 0; mf < 4; ++mf) {
        const int row_lo = n0 + wm * 64 + mf * 16 + (lane >> 2);
        float* p_lo = out + (size_t)row_lo * MDIM;
        float* p_hi = p_lo + 8 * MDIM;
#pragma unroll
        for (int nf = 0; nf < 4; ++nf) {
            const int col = m0 + wn * 32 + nf * 8 + 2 * (lane & 3);
            float2 lo, hi;
            lo.x = (float)acc[mf][nf][0] * eff + bv[nf].x;
            lo.y = (float)acc[mf][nf][1] * eff + bv[nf].y;
            hi.x = (float)acc[mf][nf][2] * eff + bv[nf].x;
            hi.y = (float)acc[mf][nf][3] * eff + bv[nf].y;
            *reinterpret_cast<float2*>(p_lo + col) = lo;
            *reinterpret_cast<float2*>(p_hi + col) = hi;
        }
    }
}

// ============================================================================
// Launch
// ============================================================================
extern "C" void kernel_launch(void* const* d_in, const int* in_sizes, int n_in,
                              void* d_out, int out_size) {
    const float* x    = (const float*)d_in[0];
    const void*  wt   = d_in[1];
    const float* bias = (const float*)d_in[2];
    float*       out  = (float*)d_out;

    cudaFuncSetAttribute(gemm_kernel, cudaFuncAttributeMaxDynamicSharedMemorySize,
                         SMEM_TOTAL);

    {
        int n4 = (N_TOK * KDIM) / 4;
        quant_kernel<<<(n4 + 255) / 256, 256>>>(x);
    }
    {
        dim3 grid(KDIM / 32, MDIM / 32);
        wtrans_kernel<<<grid, 256>>>(wt);
    }
    {
        dim3 grid(MDIM / TN, N_TOK / TM);   // (12, 256) = 3072 tiles
        gemm_kernel<<<grid, 128, SMEM_TOTAL>>>(bias, out);
    }
    (void)in_sizes; (void)n_in; (void)out_size;
}